// round 9
// baseline (speedup 1.0000x reference)
#include <cuda_runtime.h>

#define DD 8
#define BB 4096
#define VV 1024
#define K_SEL 102
#define THREADS 256
#define NROWS (DD * BB)

__device__ int g_samples[NROWS];

__device__ __forceinline__ unsigned fkey(float f) {
    unsigned b = __float_as_uint(f);
    return (b & 0x80000000u) ? ~b : (b | 0x80000000u);
}
__device__ __forceinline__ float keyf(unsigned k) {
    unsigned b = (k & 0x80000000u) ? (k & 0x7FFFFFFFu) : ~k;
    return __uint_as_float(b);
}

__global__ __launch_bounds__(THREADS)
void decode_kernel(const float* __restrict__ logits,
                   const float* __restrict__ uin,
                   const int* __restrict__ curv,
                   float* __restrict__ out_probs,
                   int write_probs)
{
    const int r    = blockIdx.x;            // r = d*B + b
    const int tid  = threadIdx.x;
    const int lane = tid & 31;
    const int wid  = tid >> 5;
    const float NEG = __int_as_float(0xff800000);
    const size_t base = (size_t)r * VV;
    const int cur = curv[r];
    const unsigned FULL = 0xffffffffu;

    __shared__ int sh_hist[4][256];          // one page per radix pass: no resets
    __shared__ int sh_wsum[8];
    __shared__ unsigned sh_sel;
    __shared__ int sh_krem;
    __shared__ int sh_cnt;
    __shared__ unsigned sh_maxbin;
    __shared__ unsigned long long sh_best;
    __shared__ float sh_red[8];
    __shared__ float sh_logZ, sh_invt;

#pragma unroll
    for (int p = 0; p < 4; ++p) sh_hist[p][tid] = 0;
    if (tid == 0) sh_best = 0ull;

    // ---- load logits once (vectorized); u loaded lazily later ----
    float4 lv = ((const float4*)(logits + base))[tid];
    float vals[4] = {lv.x, lv.y, lv.z, lv.w};
    const int vbase = tid * 4;

    unsigned keys[4];
#pragma unroll
    for (int j = 0; j < 4; ++j) {
        int v = vbase + j;
        if (v < cur || v == 0) vals[j] = NEG;
        keys[j] = fkey(vals[j]);
    }
    __syncthreads();                          // hist pages zeroed, sh_best init

    // ---- exact k-th threshold: radix select, pass-specialized, early exit ----
    unsigned prefix = 0u;
    int krem = K_SEL;
#pragma unroll
    for (int pass = 0; pass < 4; ++pass) {
        const int shift = 24 - 8 * pass;
        if (pass == 0) {
#pragma unroll
            for (int j = 0; j < 4; ++j)
                atomicAdd(&sh_hist[0][keys[j] >> 24], 1);
        } else {
            const unsigned pm = 0xFFFFFFFFu << (shift + 8);
#pragma unroll
            for (int j = 0; j < 4; ++j)
                if ((keys[j] & pm) == prefix)
                    atomicAdd(&sh_hist[pass][(keys[j] >> shift) & 0xFFu], 1);
        }
        __syncthreads();
        int cnt = sh_hist[pass][tid];
        int x = cnt;                          // warp suffix scan (inclusive)
#pragma unroll
        for (int off = 1; off < 32; off <<= 1) {
            int y = __shfl_down_sync(FULL, x, off);
            if (lane + off < 32) x += y;
        }
        if (lane == 0) sh_wsum[wid] = x;
        __syncthreads();
        int tail = 0;
#pragma unroll
        for (int w = 1; w < 8; ++w)
            if (w > wid) tail += sh_wsum[w];
        int suffix = x + tail;                // keys in bins >= tid (within prefix)
        if (pass == 0 && suffix >= 1 && (suffix - cnt) < 1)
            sh_maxbin = (unsigned)tid;        // top non-empty bin -> softmax shift
        if (suffix >= krem && (suffix - cnt) < krem) {
            sh_sel  = (unsigned)tid;
            sh_krem = krem - (suffix - cnt);
            sh_cnt  = cnt;
        }
        __syncthreads();
        prefix |= sh_sel << shift;
        krem    = sh_krem;
        if (sh_cnt == krem) break;            // whole boundary bucket kept: exact
    }
    // kept := key >= prefix  (exact threshold or exact bucket floor)

    // m = bucket ceiling of the top non-empty bin: m >= max, within one
    // exponent of it -> exp(x - m) <= 1, softmax shift-invariant.
    const float m = keyf((sh_maxbin << 24) | 0x00FFFFFFu);

    // ---- e = exp(x-m) for kept (reused for probs); deterministic sum ----
    float e[4];
    float s = 0.f;
#pragma unroll
    for (int j = 0; j < 4; ++j) {
        e[j] = (keys[j] >= prefix) ? __expf(vals[j] - m) : 0.f;
        s += e[j];
    }
#pragma unroll
    for (int off = 16; off >= 1; off >>= 1)
        s += __shfl_down_sync(FULL, s, off);
    if (lane == 0) sh_red[wid] = s;
    __syncthreads();
    if (tid == 0) {
        float t = 0.f;
#pragma unroll
        for (int w = 0; w < 8; ++w) t += sh_red[w];
        sh_logZ = m + __logf(t);
        sh_invt = __fdividef(1.f, t);
    }
    __syncthreads();
    const float logZ = sh_logZ;
    const float invt = sh_invt;

    // ---- probs (p = e*invt) + Gumbel argmax; u loaded only for kept ----
    unsigned long long best = 0ull;
#pragma unroll
    for (int j = 0; j < 4; ++j) {
        if (keys[j] >= prefix) {
            int idx = vbase + j;
            float u  = __ldg(uin + base + idx);
            float g  = -__logf(-__logf(u + 1e-20f) + 1e-20f);
            float sc = (vals[j] - logZ) + g;   // same expr as reference
            unsigned long long k64 =
                ((unsigned long long)fkey(sc) << 32) |
                (unsigned long long)(0xFFFFFFFFu - (unsigned)idx);
            if (k64 > best) best = k64;
        }
    }
    if (best) atomicMax(&sh_best, best);
    if (write_probs)
        ((float4*)(out_probs + base))[tid] =
            make_float4(e[0] * invt, e[1] * invt, e[2] * invt, e[3] * invt);
    __syncthreads();
    if (tid == 0)
        g_samples[r] = (int)(0xFFFFFFFFu - (unsigned)(sh_best & 0xFFFFFFFFull));
}

__global__ void tokens_kernel(float* __restrict__ out_tok)
{
    int i = blockIdx.x * blockDim.x + threadIdx.x;   // i in [0, B*D)
    if (i >= BB * DD) return;
    int b = i / DD, d = i % DD;
    int s0 = g_samples[b];
    int sd = g_samples[d * BB + b];
    int val = (d == 0 || s0 == 1) ? sd : 0;          // NOTE_TYPE == 1
    out_tok[i] = (float)val;                         // tokens.T flattened [B,D]
}

extern "C" void kernel_launch(void* const* d_in, const int* in_sizes, int n_in,
                              void* d_out, int out_size)
{
    const float* logits = (const float*)d_in[0];
    const float* uin    = (const float*)d_in[1];
    const int*   curv   = (const int*)d_in[2];
    float* out = (float*)d_out;

    const size_t probsN = (size_t)DD * BB * VV;
    const size_t tokN   = (size_t)BB * DD;

    float* out_tok = nullptr;
    float* out_probs = nullptr;
    if ((size_t)out_size >= probsN + tokN) {        // concat: tokens.T then probs
        out_tok = out; out_probs = out + tokN;
    } else if ((size_t)out_size >= probsN) {        // probs only
        out_probs = out;
    } else {                                        // tokens only
        out_tok = out;
    }

    decode_kernel<<<NROWS, THREADS>>>(logits, uin, curv,
                                      out_probs ? out_probs : out,
                                      out_probs != nullptr ? 1 : 0);
    if (out_tok)
        tokens_kernel<<<(BB * DD + 255) / 256, 256>>>(out_tok);
}